// round 5
// baseline (speedup 1.0000x reference)
#include <cuda_runtime.h>

// Problem shape (fixed by reference): B=64, M=64, P=128, V=32.
// Output = 0.5 * min over (m,p) of point-polygon distance, BATCH 63 ONLY.
#define BN 64
#define MN 64
#define PN 128
#define VN 32
#define EPSF 1e-12f

// Sentinel = NaN bit pattern; candidate values are finite >= 0 so their bit
// patterns are always < SENT. The slot value doubles as the ready flag.
#define SENT 0xFFFFFFFFu
#define S8   SENT,SENT,SENT,SENT,SENT,SENT,SENT,SENT
#define S64  S8,S8,S8,S8,S8,S8,S8,S8

// One slot per producer warp (2 warps x 128 blocks). Static init = module image,
// no allocation. Finalizer restores sentinels each replay -> deterministic.
__device__ unsigned g_slot[2 * PN] = { S64, S64, S64, S64 };

__global__ void __launch_bounds__(MN)
pl_fused(const float* __restrict__ last_point,
         const float* __restrict__ polygon_coords,
         float* __restrict__ out) {
    volatile unsigned* vslot = (volatile unsigned*)g_slot;
    const int t = threadIdx.x;

    if (blockIdx.x == PN) {
        // ── Finalizer block: spin on the 256 per-warp slots, reduce, write out.
        __shared__ float s_warpmin[MN / 32];
        unsigned best = 0x7F800000u;  // +inf bits
#pragma unroll
        for (int i = 0; i < 4; ++i) {
            const int idx = t + i * MN;
            unsigned v;
            while ((v = vslot[idx]) == SENT) { }
            best = umin(best, v);      // bits >= 0 floats: bit order == numeric
            vslot[idx] = SENT;         // self-reset for next replay
        }
        const unsigned wv = __reduce_min_sync(0xFFFFFFFFu, best);
        if ((t & 31) == 0) s_warpmin[t >> 5] = __uint_as_float(wv);
        __syncthreads();
        if (t == 0) {
            const float m = fminf(s_warpmin[0], s_warpmin[1]);
            out[0] = 0.5f * sqrtf(m);  // sqrt(0)==0 keeps inside-case exact
        }
        return;
    }

    // ── Producer block: polygon p of batch 63 vs all 64 points.
    __shared__ float4 s_e0[VN];   // { ax, ay, abx, aby }
    __shared__ float4 s_e1[VN];   // { inv2, invdy, by, - }

    const int p = blockIdx.x;

    // Hoist point load: last_point[63, t, :] (latency overlaps edge-table build).
    const float2 pt = reinterpret_cast<const float2*>(last_point)[(BN - 1) * MN + t];
    const float px = pt.x;
    const float py = pt.y;

    const float2* pc = reinterpret_cast<const float2*>(polygon_coords)
                       + (((BN - 1) * PN + p) * VN);

    if (t < VN) {
        const float2 a = pc[t];
        const float2 b = pc[(t + 1) & (VN - 1)];   // roll(-1) over vertex axis
        const float abx = b.x - a.x;
        const float aby = b.y - a.y;
        s_e0[t] = make_float4(a.x, a.y, abx, aby);
        s_e1[t] = make_float4(1.0f / (abx * abx + aby * aby + EPSF),
                              1.0f / (aby + EPSF),
                              b.y, 0.0f);
    }
    __syncthreads();

    float mindd = 3.402823466e+38f;
    int crossings = 0;

#pragma unroll
    for (int v = 0; v < VN; ++v) {
        const float4 e0 = s_e0[v];   // ax, ay, abx, aby
        const float4 e1 = s_e1[v];   // inv2, invdy, by
        const float apx = px - e0.x;
        const float apy = py - e0.y;

        // Squared segment distance (sqrt deferred to finalizer — monotone).
        float tt = (apx * e0.z + apy * e0.w) * e1.x;
        tt = fminf(fmaxf(tt, 0.0f), 1.0f);
        const float dx = apx - tt * e0.z;
        const float dy = apy - tt * e0.w;
        mindd = fminf(mindd, dx * dx + dy * dy);

        // Ray-crossing (even-odd) test; apy reused as (py - ay).
        const bool straddles = (e0.y > py) != (e1.z > py);
        const float x_int = e0.x + e0.z * (apy * e1.y);
        if (straddles && (px < x_int)) ++crossings;
    }

    // Candidate: exact 0 if inside (matches jnp.where), else max(mindd, EPS)
    // so the deferred sqrt reproduces sqrt(maximum(dd, EPS)) exactly.
    const float cand = ((crossings & 1) != 0) ? 0.0f : fmaxf(mindd, EPSF);

    // Per-warp min -> per-warp slot. No block combine, no atomics, no fence
    // (single word: the value IS the flag).
    const unsigned uv = __reduce_min_sync(0xFFFFFFFFu, __float_as_uint(cand));
    if ((t & 31) == 0)
        vslot[p * 2 + (t >> 5)] = uv;
}

extern "C" void kernel_launch(void* const* d_in, const int* in_sizes, int n_in,
                              void* d_out, int out_size) {
    const float* last_point     = (const float*)d_in[0];  // [64, 64, 2] f32
    const float* polygon_coords = (const float*)d_in[1];  // [64, 128, 32, 2] f32
    float* out = (float*)d_out;                           // scalar f32 output

    pl_fused<<<PN + 1, MN>>>(last_point, polygon_coords, out);
}

// round 6
// speedup vs baseline: 1.3413x; 1.3413x over previous
#include <cuda_runtime.h>

// Problem shape (fixed by reference): B=64, M=64, P=128, V=32.
// Output = 0.5 * min over (m,p) of point-polygon distance, BATCH 63 ONLY.
#define BN 64
#define MN 64
#define PN 128
#define VN 32
#define EPSF 1e-12f

// Per-block minima (squared distance, or exact 0 if a point is inside).
// Plain stores to distinct slots — no same-address atomic serialization.
__device__ float g_blockmin[PN];

__global__ void __launch_bounds__(MN)
pl_main(const float* __restrict__ last_point,
        const float* __restrict__ polygon_coords) {
    // Edge tables packed for 2x LDS.128 per edge (broadcast reads, conflict-free).
    __shared__ float4 s_e0[VN];   // { ax, ay, abx, aby }
    __shared__ float4 s_e1[VN];   // { inv2, invdy, by, - }
    __shared__ float  s_warpmin[MN / 32];

    const int p = blockIdx.x;
    const int t = threadIdx.x;

    // Hoist point load: last_point[63, t, :] (latency overlaps edge-table build).
    const float2 pt = reinterpret_cast<const float2*>(last_point)[(BN - 1) * MN + t];
    const float px = pt.x;
    const float py = pt.y;

    // Polygon p of batch 63: vertices are contiguous float2.
    const float2* pc = reinterpret_cast<const float2*>(polygon_coords)
                       + (((BN - 1) * PN + p) * VN);

    if (t < VN) {
        const float2 a = pc[t];
        const float2 b = pc[(t + 1) & (VN - 1)];   // roll(-1) over vertex axis
        const float abx = b.x - a.x;
        const float aby = b.y - a.y;
        s_e0[t] = make_float4(a.x, a.y, abx, aby);
        s_e1[t] = make_float4(1.0f / (abx * abx + aby * aby + EPSF),
                              1.0f / (aby + EPSF),
                              b.y, 0.0f);
    }
    __syncthreads();

    float mindd = 3.402823466e+38f;
    int crossings = 0;

#pragma unroll
    for (int v = 0; v < VN; ++v) {
        const float4 e0 = s_e0[v];   // ax, ay, abx, aby
        const float4 e1 = s_e1[v];   // inv2, invdy, by
        const float apx = px - e0.x;
        const float apy = py - e0.y;

        // Squared segment distance (sqrt deferred to finalize — monotone).
        float tt = (apx * e0.z + apy * e0.w) * e1.x;
        tt = fminf(fmaxf(tt, 0.0f), 1.0f);
        const float dx = apx - tt * e0.z;
        const float dy = apy - tt * e0.w;
        mindd = fminf(mindd, dx * dx + dy * dy);

        // Ray-crossing (even-odd) test; apy reused as (py - ay).
        const bool straddles = (e0.y > py) != (e1.z > py);
        const float x_int = e0.x + e0.z * (apy * e1.y);
        if (straddles && (px < x_int)) ++crossings;
    }

    // Candidate: exact 0 if inside (matches jnp.where), else max(mindd, EPS)
    // so the deferred sqrt reproduces sqrt(maximum(dd, EPS)) exactly.
    const float cand = ((crossings & 1) != 0) ? 0.0f : fmaxf(mindd, EPSF);

    // Block min: single redux per warp (bits of non-neg floats order numerically).
    const unsigned uv = __reduce_min_sync(0xFFFFFFFFu, __float_as_uint(cand));
    if ((t & 31) == 0) s_warpmin[t >> 5] = __uint_as_float(uv);
    __syncthreads();

    if (t == 0)
        g_blockmin[p] = fminf(s_warpmin[0], s_warpmin[1]);  // plain STG, distinct slot

    __syncthreads();  // order t0's store before every thread's trigger
    // PDL: signal the dependent finalizer that this CTA's writes are done.
    cudaTriggerProgrammaticLaunchCompletion();
}

__global__ void __launch_bounds__(PN)
pl_final(float* __restrict__ out) {
    __shared__ float s_warpmin[PN / 32];
    const int t = threadIdx.x;

    // PDL: we may have launched before pl_main finished — wait for its trigger
    // (guarantees visibility of all pre-trigger writes, i.e. g_blockmin).
    cudaGridDependencySynchronize();

    const float v = g_blockmin[t];
    const unsigned uv = __reduce_min_sync(0xFFFFFFFFu, __float_as_uint(v));
    if ((t & 31) == 0) s_warpmin[t >> 5] = __uint_as_float(uv);
    __syncthreads();

    if (t == 0) {
        float m = fminf(fminf(s_warpmin[0], s_warpmin[1]),
                        fminf(s_warpmin[2], s_warpmin[3]));
        out[0] = 0.5f * sqrtf(m);   // sqrt(0) == 0 keeps inside-case exact
    }
}

extern "C" void kernel_launch(void* const* d_in, const int* in_sizes, int n_in,
                              void* d_out, int out_size) {
    const float* last_point     = (const float*)d_in[0];  // [64, 64, 2] f32
    const float* polygon_coords = (const float*)d_in[1];  // [64, 128, 32, 2] f32
    float* out = (float*)d_out;                           // scalar f32 output

    pl_main<<<PN, MN>>>(last_point, polygon_coords);

    // Finalizer launched with Programmatic Stream Serialization: its launch
    // ramp overlaps pl_main's execution; ordering is enforced on-device by
    // cudaGridDependencySynchronize().
    cudaLaunchConfig_t cfg = {};
    cfg.gridDim  = dim3(1, 1, 1);
    cfg.blockDim = dim3(PN, 1, 1);
    cfg.dynamicSmemBytes = 0;
    cfg.stream = 0;

    cudaLaunchAttribute attrs[1];
    attrs[0].id = cudaLaunchAttributeProgrammaticStreamSerialization;
    attrs[0].val.programmaticStreamSerializationAllowed = 1;
    cfg.attrs = attrs;
    cfg.numAttrs = 1;

    cudaLaunchKernelEx(&cfg, pl_final, out);
}